// round 1
// baseline (speedup 1.0000x reference)
#include <cuda_runtime.h>
#include <cstdint>

#define TT   16384
#define ED   1024
#define HD   1024
#define G4   4096
#define NMV  128        // matvec CTAs (each owns 8 h-indices = 32 gate rows)
#define NLOSS 16        // dedicated loss CTAs
#define RTHREADS 512

// ---- scratch (static device memory; no allocations anywhere) ----
__device__ float        g_xg[TT][G4];     // 256 MB: input projections
__device__ float        g_hbuf[TT][HD];   // 64 MB: full h history
__device__ unsigned int g_cnt[TT];        // per-step completion counters
__device__ float        g_loss[TT];       // per-step losses
__device__ int          g_ys[TT];         // normalized labels (int32)

// ---- helpers ----
__device__ __forceinline__ unsigned long long ffma2(unsigned long long a,
                                                    unsigned long long b,
                                                    unsigned long long c) {
    unsigned long long d;
    asm("fma.rn.f32x2 %0, %1, %2, %3;" : "=l"(d) : "l"(a), "l"(b), "l"(c));
    return d;
}
__device__ __forceinline__ float2 unpk(unsigned long long v) {
    float2 r;
    asm("mov.b64 {%0, %1}, %2;" : "=f"(r.x), "=f"(r.y) : "l"(v));
    return r;
}
__device__ __forceinline__ unsigned int ld_acq(const unsigned int* p) {
    unsigned int v;
    asm volatile("ld.acquire.gpu.global.u32 %0, [%1];" : "=r"(v) : "l"(p) : "memory");
    return v;
}
__device__ __forceinline__ void red_rel(unsigned int* p) {
    asm volatile("red.release.gpu.global.add.u32 [%0], 1;" :: "l"(p) : "memory");
}
__device__ __forceinline__ float sigm(float x) {
    return 1.f / (1.f + __expf(-x));   // x<-88 -> expf=inf -> 0 (correct limit)
}

// ---- kernel 0: reset counters + normalize ys dtype (int64 vs int32 autodetect) ----
__global__ void __launch_bounds__(256) reset_k(const int* __restrict__ ysr) {
    int i = blockIdx.x * blockDim.x + threadIdx.x;
    bool is64 = true;
#pragma unroll
    for (int q = 1; q < 16; q += 2) is64 = is64 && (ysr[q] == 0);
    if (i < TT) {
        g_cnt[i] = 0u;
        g_ys[i]  = is64 ? ysr[2 * i] : ysr[i];
    }
}

// ---- kernel 1: xg = Xs @ W_ih^T + (b_ih + b_hh), fp32 tiled SIMT GEMM ----
// C[16384,4096]: block 128x128, BK=8, 256 threads, 8x8 per thread.
__global__ void __launch_bounds__(256) gemm_xg(const float* __restrict__ X,
                                               const float* __restrict__ W,
                                               const float* __restrict__ bih,
                                               const float* __restrict__ bhh) {
    __shared__ float As[8][128];
    __shared__ float Bs[8][128];
    const int tid = threadIdx.x;
    const int tx = tid & 15, ty = tid >> 4;
    const int bm = blockIdx.y * 128;
    const int bn = blockIdx.x * 128;
    const int lr = tid >> 1;            // 0..127
    const int lc = (tid & 1) << 2;      // 0 or 4
    const float* Ag = X + (size_t)(bm + lr) * ED + lc;
    const float* Bg = W + (size_t)(bn + lr) * ED + lc;

    float acc[8][8];
#pragma unroll
    for (int i = 0; i < 8; i++)
#pragma unroll
        for (int j = 0; j < 8; j++) acc[i][j] = 0.f;

    for (int k0 = 0; k0 < ED; k0 += 8) {
        float4 av = *(const float4*)(Ag + k0);
        float4 bv = *(const float4*)(Bg + k0);
        __syncthreads();   // previous iteration's reads complete
        As[lc + 0][lr] = av.x; As[lc + 1][lr] = av.y;
        As[lc + 2][lr] = av.z; As[lc + 3][lr] = av.w;
        Bs[lc + 0][lr] = bv.x; Bs[lc + 1][lr] = bv.y;
        Bs[lc + 2][lr] = bv.z; Bs[lc + 3][lr] = bv.w;
        __syncthreads();
#pragma unroll
        for (int kk = 0; kk < 8; kk++) {
            float a[8], b[8];
            *(float4*)(a)     = *(const float4*)&As[kk][ty * 8];
            *(float4*)(a + 4) = *(const float4*)&As[kk][ty * 8 + 4];
            *(float4*)(b)     = *(const float4*)&Bs[kk][tx * 8];
            *(float4*)(b + 4) = *(const float4*)&Bs[kk][tx * 8 + 4];
#pragma unroll
            for (int i = 0; i < 8; i++)
#pragma unroll
                for (int j = 0; j < 8; j++)
                    acc[i][j] = fmaf(a[i], b[j], acc[i][j]);
        }
    }

    const int n0 = bn + tx * 8;
    float bias[8];
#pragma unroll
    for (int j = 0; j < 8; j++) bias[j] = bih[n0 + j] + bhh[n0 + j];
#pragma unroll
    for (int i = 0; i < 8; i++) {
        const int m = bm + ty * 8 + i;
        float4 o0 = make_float4(acc[i][0] + bias[0], acc[i][1] + bias[1],
                                acc[i][2] + bias[2], acc[i][3] + bias[3]);
        float4 o1 = make_float4(acc[i][4] + bias[4], acc[i][5] + bias[5],
                                acc[i][6] + bias[6], acc[i][7] + bias[7]);
        *(float4*)&g_xg[m][n0]     = o0;
        *(float4*)&g_xg[m][n0 + 4] = o1;
    }
}

// ---- kernel 2: persistent LSTM recurrence + loss ----
// CTAs 0..127: weight-stationary matvec+activations for 8 h-indices each.
// CTAs 128..143: loss (logsumexp) consumers, off the critical path.
// Residency: 512 thr * ~100 regs -> 1 CTA/SM; 144 CTAs <= 152 SMs -> all resident.
__global__ void __launch_bounds__(RTHREADS, 1) lstm_persist(const float* __restrict__ Whh) {
    const int b   = blockIdx.x;
    const int tid = threadIdx.x;

    if (b < NMV) {
        __shared__ __align__(16) float h_s[HD];
        __shared__ float part[16][32];
        const int w = tid >> 5, l = tid & 31;
        // lane l -> gate (l>>3) in {i,f,g,o}, local j = l&7; global j = 8b + (l&7)
        const int row = ((l >> 3) << 10) + (b << 3) + (l & 7);

        // Load this thread's 64 W_hh values into registers (cols 64w .. 64w+63).
        ulonglong2 Wr[16];
        {
            const ulonglong2* wp =
                (const ulonglong2*)(Whh + (size_t)row * HD + (w << 6));
#pragma unroll
            for (int q = 0; q < 16; q++) Wr[q] = wp[q];
        }
        float cstate = 0.f;  // only meaningful on warp0 lanes 0..7
        for (int i = tid; i < HD; i += RTHREADS) h_s[i] = 0.f;
        __syncthreads();

        const ulonglong2* h_u2 = (const ulonglong2*)h_s;

        for (int t = 0; t < TT; t++) {
            float xval = 0.f;
            if (w == 0) xval = g_xg[t][row];   // issued early; consumed post-reduce

            // partial dot over cols [64w, 64w+64), packed f32x2 FMAs
            unsigned long long acc0 = 0ull, acc1 = 0ull;
#pragma unroll
            for (int q = 0; q < 16; q++) {
                ulonglong2 hh = h_u2[(w << 4) + q];   // LDS.128 broadcast
                acc0 = ffma2(Wr[q].x, hh.x, acc0);
                acc1 = ffma2(Wr[q].y, hh.y, acc1);
            }
            float2 p0 = unpk(acc0), p1 = unpk(acc1);
            part[w][l] = (p0.x + p1.x) + (p0.y + p1.y);
            __syncthreads();  // (A) partials ready

            if (w == 0) {
                // tree-reduce 16 warp partials for row(l)
                float s0 = part[0][l]  + part[1][l];
                float s1 = part[2][l]  + part[3][l];
                float s2 = part[4][l]  + part[5][l];
                float s3 = part[6][l]  + part[7][l];
                float s4 = part[8][l]  + part[9][l];
                float s5 = part[10][l] + part[11][l];
                float s6 = part[12][l] + part[13][l];
                float s7 = part[14][l] + part[15][l];
                float u0 = (s0 + s1) + (s2 + s3);
                float u1 = (s4 + s5) + (s6 + s7);
                float gpre = xval + (u0 + u1);

                const int jj = l & 7;
                float pi = __shfl_sync(0xffffffffu, gpre, jj);
                float pf = __shfl_sync(0xffffffffu, gpre, jj + 8);
                float pg = __shfl_sync(0xffffffffu, gpre, jj + 16);
                float po = __shfl_sync(0xffffffffu, gpre, jj + 24);
                if (l < 8) {
                    float ig = sigm(pi);
                    float fg = sigm(pf);
                    float gg = tanhf(pg);
                    float og = sigm(po);
                    cstate = fmaf(fg, cstate, ig * gg);
                    float hv = og * tanhf(cstate);
                    g_hbuf[t][(b << 3) + l] = hv;
                }
                __syncwarp();
                if (l == 0) red_rel(&g_cnt[t]);  // publish slice (release)
            }
            if (tid == 0) {
                while (ld_acq(&g_cnt[t]) < NMV) { }
            }
            __syncthreads();  // (B) step t globally complete

            if (t + 1 < TT && tid < 256) {
                float4 hv = ((const float4*)g_hbuf[t])[tid];
                ((float4*)h_s)[tid] = hv;
            }
            __syncthreads();  // (C) h_s holds h_t for step t+1
        }
    } else {
        // ---- loss CTA ----
        __shared__ float sred[RTHREADS];
        const int lcta = b - NMV;
        for (int t = lcta; t < TT; t += NLOSS) {
            if (tid == 0) {
                while (ld_acq(&g_cnt[t]) < NMV) { }
            }
            __syncthreads();
            float v0 = g_hbuf[t][2 * tid];
            float v1 = g_hbuf[t][2 * tid + 1];
            sred[tid] = __expf(v0) + __expf(v1);
            __syncthreads();
            for (int s = RTHREADS / 2; s >= 32; s >>= 1) {
                if (tid < s) sred[tid] += sred[tid + s];
                __syncthreads();
            }
            if (tid < 32) {
                float v = sred[tid];
                v += __shfl_down_sync(0xffffffffu, v, 16);
                v += __shfl_down_sync(0xffffffffu, v, 8);
                v += __shfl_down_sync(0xffffffffu, v, 4);
                v += __shfl_down_sync(0xffffffffu, v, 2);
                v += __shfl_down_sync(0xffffffffu, v, 1);
                if (tid == 0) {
                    int y = g_ys[t];
                    g_loss[t] = __logf(v) - g_hbuf[t][y];  // h in (-1,1): no max needed
                }
            }
            __syncthreads();
        }
    }
}

// ---- kernel 3: deterministic final sum ----
__global__ void __launch_bounds__(256) finalize_k(float* __restrict__ out) {
    __shared__ float sr[256];
    const int tid = threadIdx.x;
    float s = 0.f;
    for (int i = tid; i < TT; i += 256) s += g_loss[i];
    sr[tid] = s;
    __syncthreads();
    for (int st = 128; st >= 1; st >>= 1) {
        if (tid < st) sr[tid] += sr[tid + st];
        __syncthreads();
    }
    if (tid == 0) out[0] = sr[0];
}

// ---- entry point ----
extern "C" void kernel_launch(void* const* d_in, const int* in_sizes, int n_in,
                              void* d_out, int out_size) {
    const float* Xs  = (const float*)d_in[0];
    const float* Wih = (const float*)d_in[1];
    const float* Whh = (const float*)d_in[2];
    const float* bih = (const float*)d_in[3];
    const float* bhh = (const float*)d_in[4];
    const int*   ysr = (const int*)d_in[5];

    reset_k<<<TT / 256, 256>>>(ysr);
    gemm_xg<<<dim3(G4 / 128, TT / 128), 256>>>(Xs, Wih, bih, bhh);
    lstm_persist<<<NMV + NLOSS, RTHREADS>>>(Whh);
    finalize_k<<<1, 256>>>((float*)d_out);
}